// round 12
// baseline (speedup 1.0000x reference)
#include <cuda_runtime.h>
#include <cuda_bf16.h>
#include <math.h>

#define BATCH  256
#define SEQ    256
#define IN_DIM 128
#define HID    1024
#define NOUT   10
#define MROWS  (BATCH * SEQ)

// ---------------------------------------------------------------------------
// Global scratch
// ---------------------------------------------------------------------------
__device__ float g_xproj[(size_t)SEQ * BATCH * HID];                  // [s][b][h] fp32
__device__ __align__(16) __nv_bfloat16 g_Ahi[2][BATCH * HID];         // h hi (ping-pong)
__device__ __align__(16) __nv_bfloat16 g_Alo[2][BATCH * HID];         // h lo
__device__ __align__(16) __nv_bfloat16 g_BThi[HID * HID];             // Whh^T hi [n][k]
__device__ __align__(16) __nv_bfloat16 g_BTlo[HID * HID];             // Whh^T lo [n][k]
__device__ __align__(16) __nv_bfloat16 g_BXhi[HID * IN_DIM];          // Whx^T hi [n][k]
__device__ __align__(16) __nv_bfloat16 g_BXlo[HID * IN_DIM];          // Whx^T lo [n][k]
__device__ __align__(16) __nv_bfloat16 g_Xhi[(size_t)MROWS * IN_DIM]; // x hi [m][k]
__device__ __align__(16) __nv_bfloat16 g_Xlo[(size_t)MROWS * IN_DIM]; // x lo
__device__ unsigned g_barv[8][16];                                    // per (mg, ng) step counters

// ---------------------------------------------------------------------------
// helpers
// ---------------------------------------------------------------------------
__device__ __forceinline__ void cp_async16(void* smem_dst, const void* gmem_src) {
    unsigned sa = (unsigned)__cvta_generic_to_shared(smem_dst);
    asm volatile("cp.async.cg.shared.global [%0], [%1], 16;\n" :: "r"(sa), "l"(gmem_src));
}
__device__ __forceinline__ void cp_commit() { asm volatile("cp.async.commit_group;\n"); }
template <int N>
__device__ __forceinline__ void cp_wait() { asm volatile("cp.async.wait_group %0;\n" :: "n"(N)); }

__device__ __forceinline__ void ldsm_x4(unsigned& r0, unsigned& r1, unsigned& r2, unsigned& r3,
                                        const void* p) {
    unsigned a = (unsigned)__cvta_generic_to_shared(p);
    asm volatile("ldmatrix.sync.aligned.m8n8.x4.shared.b16 {%0,%1,%2,%3}, [%4];"
                 : "=r"(r0), "=r"(r1), "=r"(r2), "=r"(r3) : "r"(a));
}
__device__ __forceinline__ void mma_bf16(float* c, const unsigned* a, unsigned b0, unsigned b1) {
    asm volatile(
        "mma.sync.aligned.m16n8k16.row.col.f32.bf16.bf16.f32 "
        "{%0,%1,%2,%3}, {%4,%5,%6,%7}, {%8,%9}, {%0,%1,%2,%3};"
        : "+f"(c[0]), "+f"(c[1]), "+f"(c[2]), "+f"(c[3])
        : "r"(a[0]), "r"(a[1]), "r"(a[2]), "r"(a[3]), "r"(b0), "r"(b1));
}
__device__ __forceinline__ void split2(float v, __nv_bfloat16& hi, __nv_bfloat16& lo) {
    hi = __float2bfloat16(v);
    lo = __float2bfloat16(v - __bfloat162float(hi));
}
__device__ __forceinline__ void poll_gpu(const unsigned* p, unsigned need) {
    unsigned v;
    do {
        asm volatile("ld.acquire.gpu.u32 %0, [%1];" : "=r"(v) : "l"(p));
    } while (v < need);
}
__device__ __forceinline__ void wait_flag(const unsigned* f) {
    unsigned a = (unsigned)__cvta_generic_to_shared(f);
    unsigned v;
    do {
        asm volatile("ld.acquire.cta.shared::cta.b32 %0, [%1];" : "=r"(v) : "r"(a));
    } while (!v);
}

// ---------------------------------------------------------------------------
// Prep kernels: weight splits (transposed), x split
// ---------------------------------------------------------------------------
__global__ __launch_bounds__(256) void split_whh_kernel(const float* __restrict__ W)
{
    __shared__ float tile[32][33];
    const int n0 = blockIdx.x * 32, k0 = blockIdx.y * 32;
    const int tx = threadIdx.x, ty = threadIdx.y;
    #pragma unroll
    for (int i = 0; i < 4; i++)
        tile[ty + i * 8][tx] = W[(size_t)(k0 + ty + i * 8) * HID + n0 + tx];
    __syncthreads();
    #pragma unroll
    for (int i = 0; i < 4; i++) {
        int n = n0 + ty + i * 8, k = k0 + tx;
        __nv_bfloat16 hi, lo; split2(tile[tx][ty + i * 8], hi, lo);
        g_BThi[(size_t)n * HID + k] = hi;
        g_BTlo[(size_t)n * HID + k] = lo;
    }
}

__global__ __launch_bounds__(256) void split_whx_kernel(const float* __restrict__ W)
{
    __shared__ float tile[32][33];
    const int n0 = blockIdx.x * 32, k0 = blockIdx.y * 32;
    const int tx = threadIdx.x, ty = threadIdx.y;
    #pragma unroll
    for (int i = 0; i < 4; i++)
        tile[ty + i * 8][tx] = W[(size_t)(k0 + ty + i * 8) * HID + n0 + tx];
    __syncthreads();
    #pragma unroll
    for (int i = 0; i < 4; i++) {
        int n = n0 + ty + i * 8, k = k0 + tx;
        __nv_bfloat16 hi, lo; split2(tile[tx][ty + i * 8], hi, lo);
        g_BXhi[(size_t)n * IN_DIM + k] = hi;
        g_BXlo[(size_t)n * IN_DIM + k] = lo;
    }
}

__global__ __launch_bounds__(256) void xsplit_kernel(const float* __restrict__ x)
{
    size_t i = ((size_t)blockIdx.x * 256 + threadIdx.x) * 4;
    float4 v = *reinterpret_cast<const float4*>(&x[i]);
    __nv_bfloat16 h0,h1,h2,h3,l0,l1,l2,l3;
    split2(v.x,h0,l0); split2(v.y,h1,l1); split2(v.z,h2,l2); split2(v.w,h3,l3);
    __nv_bfloat162 a,b,c,d;
    a.x=h0; a.y=h1; b.x=h2; b.y=h3; c.x=l0; c.y=l1; d.x=l2; d.y=l3;
    *reinterpret_cast<__nv_bfloat162*>(&g_Xhi[i])     = a;
    *reinterpret_cast<__nv_bfloat162*>(&g_Xhi[i + 2]) = b;
    *reinterpret_cast<__nv_bfloat162*>(&g_Xlo[i])     = c;
    *reinterpret_cast<__nv_bfloat162*>(&g_Xlo[i + 2]) = d;
}

// ---------------------------------------------------------------------------
// xproj via bf16 MMA (3-term split), B-stationary:
// CTA persists B slice (256N x 128K hi/lo) in smem, loops 4 M-tiles of 64.
// 256 thr = 8 warps (2M x 4N, warp 32x64). Grid (4, 256).
// ---------------------------------------------------------------------------
#define XP_BE   (256 * 136)
#define XP_AE   (64 * 136)
#define XP_SMEM ((2 * XP_BE + 4 * XP_AE) * 2)

__global__ __launch_bounds__(256) void xproj_mma_kernel(const float* __restrict__ bh)
{
    extern __shared__ __align__(16) char sm_raw[];
    __nv_bfloat16* sBh = (__nv_bfloat16*)sm_raw;     // [256][136]
    __nv_bfloat16* sBl = sBh + XP_BE;
    __nv_bfloat16* sAh = sBl + XP_BE;                // [2][64][136]
    __nv_bfloat16* sAl = sAh + 2 * XP_AE;

    const int n0 = blockIdx.x * 256;
    const int mbase = blockIdx.y * 256;
    const int tid = threadIdx.x, lane = tid & 31, wid = tid >> 5;
    const int wm = wid >> 2, wn = wid & 3;
    const int lt = lane >> 3, lr = lane & 7;
    const int g = lane >> 2, t2 = (lane & 3) * 2;
    const int a_sub = (lt & 1) * 8 + lr, a_cs = (lt >> 1) * 8;
    const int b_sub = (lt >> 1) * 8 + lr, b_cs = (lt & 1) * 8;

    auto stageA = [&](int mt, int buf) {
        const int m0 = mbase + mt * 64;
        #pragma unroll
        for (int i = 0; i < 4; i++) {
            int p = tid + i * 256, r = p >> 4, c = p & 15;
            cp_async16(&sAh[buf * XP_AE + r * 136 + c * 8],
                       &g_Xhi[(size_t)(m0 + r) * IN_DIM + c * 8]);
            cp_async16(&sAl[buf * XP_AE + r * 136 + c * 8],
                       &g_Xlo[(size_t)(m0 + r) * IN_DIM + c * 8]);
        }
    };

    // stage B (persistent) + A tile 0
    #pragma unroll
    for (int i = 0; i < 16; i++) {
        int p = tid + i * 256, r = p >> 4, c = p & 15;
        cp_async16(&sBh[r * 136 + c * 8], &g_BXhi[(size_t)(n0 + r) * IN_DIM + c * 8]);
        cp_async16(&sBl[r * 136 + c * 8], &g_BXlo[(size_t)(n0 + r) * IN_DIM + c * 8]);
    }
    stageA(0, 0);
    cp_commit();

    for (int mt = 0; mt < 4; mt++) {
        const int buf = mt & 1;
        if (mt < 3) { stageA(mt + 1, (mt + 1) & 1); cp_commit(); cp_wait<1>(); }
        else        { cp_wait<0>(); }
        __syncthreads();

        float c_[2][8][4];
        #pragma unroll
        for (int i = 0; i < 2; i++)
            #pragma unroll
            for (int j = 0; j < 8; j++)
                #pragma unroll
                for (int q = 0; q < 4; q++) c_[i][j][q] = 0.f;

        #pragma unroll
        for (int kk = 0; kk < IN_DIM; kk += 16) {
            unsigned ah2[2][4], al2[2][4], bhf[4][4], blf[4][4];
            #pragma unroll
            for (int mi = 0; mi < 2; mi++) {
                int row = wm * 32 + mi * 16 + a_sub;
                ldsm_x4(ah2[mi][0], ah2[mi][1], ah2[mi][2], ah2[mi][3],
                        &sAh[buf * XP_AE + row * 136 + kk + a_cs]);
                ldsm_x4(al2[mi][0], al2[mi][1], al2[mi][2], al2[mi][3],
                        &sAl[buf * XP_AE + row * 136 + kk + a_cs]);
            }
            #pragma unroll
            for (int p = 0; p < 4; p++) {
                int row = wn * 64 + p * 16 + b_sub;
                ldsm_x4(bhf[p][0], bhf[p][1], bhf[p][2], bhf[p][3], &sBh[row * 136 + kk + b_cs]);
                ldsm_x4(blf[p][0], blf[p][1], blf[p][2], blf[p][3], &sBl[row * 136 + kk + b_cs]);
            }
            #pragma unroll
            for (int mi = 0; mi < 2; mi++)
                #pragma unroll
                for (int nt = 0; nt < 8; nt++) {
                    int p = nt >> 1, q = (nt & 1) * 2;
                    mma_bf16(c_[mi][nt], ah2[mi], bhf[p][q], bhf[p][q + 1]);
                    mma_bf16(c_[mi][nt], ah2[mi], blf[p][q], blf[p][q + 1]);
                    mma_bf16(c_[mi][nt], al2[mi], bhf[p][q], bhf[p][q + 1]);
                }
        }
        __syncthreads();   // A-buf reads done before next stage overwrites

        const int m0 = mbase + mt * 64;
        #pragma unroll
        for (int mi = 0; mi < 2; mi++)
            #pragma unroll
            for (int nt = 0; nt < 8; nt++) {
                int n_e = n0 + wn * 64 + nt * 8 + t2;
                float2 bb = *reinterpret_cast<const float2*>(&bh[n_e]);
                #pragma unroll
                for (int rr = 0; rr < 2; rr++) {
                    int m_e = m0 + wm * 32 + mi * 16 + g + rr * 8;
                    int b_ = m_e >> 8, s = m_e & 255;
                    float2 o;
                    o.x = c_[mi][nt][rr * 2 + 0] + bb.x;
                    o.y = c_[mi][nt][rr * 2 + 1] + bb.y;
                    *reinterpret_cast<float2*>(
                        &g_xproj[((size_t)s * BATCH + b_) * HID + n_e]) = o;
                }
            }
    }
}

// ---------------------------------------------------------------------------
// Step 0: h = tanh(xproj_0) -> buf 0; reset all (mg, ng) counters.
// ---------------------------------------------------------------------------
__global__ void step0_kernel()
{
    if (blockIdx.x == 0 && threadIdx.x < 128)
        ((unsigned*)g_barv)[threadIdx.x] = 0;
    int i = blockIdx.x * blockDim.x + threadIdx.x;
    float h = tanhf(g_xproj[i]);
    __nv_bfloat16 hi, lo; split2(h, hi, lo);
    g_Ahi[0][i] = hi;
    g_Alo[0][i] = lo;
}

// ---------------------------------------------------------------------------
// Persistent RNN kernel: steps t=1..255. 128 CTAs (8 mg x 16 ng), CTA tile
// 32M x 64N, 256 thr. 8 warps = 2M x 2N positions of 16x32 warp tiles with
// 2-way K-split. Whh^T hi persistent in smem; Whh^T lo + A streamed.
// Fine-grained sync: per-(mg,ng) counters; chunk c needs only producers
// ng'=2c,2c+1. Rotated chunk order starting at own columns; 8 warps poll
// producers concurrently at step start -> smem flags; stage guards spin on
// smem (cheap). Self-producer skipped (program order).
// ---------------------------------------------------------------------------
#define P_BPER_E (64 * 1032)
#define P_BLO_E  (64 * 136)
#define P_A_E    (32 * 136)
#define P_SMEM   ((P_BPER_E + 2 * P_BLO_E + 4 * P_A_E) * 2 + 4 * 32 * 17 * 4 + 64)

__global__ __launch_bounds__(256) void rnn_persist_kernel()
{
    extern __shared__ __align__(16) char sm_raw[];
    __nv_bfloat16* sBper = (__nv_bfloat16*)sm_raw;       // [64][1032]
    __nv_bfloat16* sBlo  = sBper + P_BPER_E;             // [2][64][136]
    __nv_bfloat16* sAh   = sBlo + 2 * P_BLO_E;           // [2][32][136]
    __nv_bfloat16* sAl   = sAh + 2 * P_A_E;              // [2][32][136]
    float*         sRed  = (float*)(sAl + 2 * P_A_E);    // [4][32][17]
    unsigned*      sReady = (unsigned*)(sRed + 4 * 32 * 17); // [2][8] parity flags

    const int bx = blockIdx.x;
    const int ng = bx >> 3, mg = bx & 7;
    const int n0 = ng * 64, m0 = mg * 32;
    const int c0 = ng >> 1;                    // own-columns chunk

    const int tid = threadIdx.x, lane = tid & 31, wid = tid >> 5;
    const int wm = wid & 1;            // M position (16 rows)
    const int wn = (wid >> 1) & 1;     // N position (32 cols)
    const int ks = wid >> 2;           // K-split half
    const int pos = wm * 2 + wn;
    const int lt = lane >> 3, lr = lane & 7;
    const int g = lane >> 2, t2 = (lane & 3) * 2;
    const int a_row = wm * 16 + (lt & 1) * 8 + lr;
    const int a_cs  = (lt >> 1) * 8;
    const int b_sub = (lt >> 1) * 8 + lr;
    const int b_cs  = (lt & 1) * 8;
    const int m_e0  = m0 + wm * 16 + g;
    const int n_e0  = n0 + wn * 32 + t2;

    // ---- load persistent Whh^T hi slice (64 x 1024); init flags
    #pragma unroll
    for (int i = 0; i < 32; i++) {
        int p = tid + i * 256, r = p >> 7, c = p & 127;
        cp_async16(&sBper[r * 1032 + c * 8], &g_BThi[(size_t)(n0 + r) * HID + c * 8]);
    }
    if (tid < 16) sReady[tid] = 0;
    cp_commit(); cp_wait<0>(); __syncthreads();

    for (int t = 1; t < SEQ; t++) {
        const int par = t & 1;
        unsigned* rdy = &sReady[par * 8];
        const __nv_bfloat16* __restrict__ Ah_r = g_Ahi[(t - 1) & 1];
        const __nv_bfloat16* __restrict__ Al_r = g_Alo[(t - 1) & 1];
        __nv_bfloat16* __restrict__ Ah_w = g_Ahi[t & 1];
        __nv_bfloat16* __restrict__ Al_w = g_Alo[t & 1];
        const float* __restrict__ xp = &g_xproj[(size_t)t * BATCH * HID];

        auto rc = [&](int j) { return (c0 + j) & 7; };

        auto stageA = [&](int c, int buf) {
            const int k0 = c * 128;
            #pragma unroll
            for (int i = 0; i < 2; i++) {
                int p = tid + i * 256, r = p >> 4, cc = p & 15;
                cp_async16(&sAh[buf * P_A_E + r * 136 + cc * 8],
                           &Ah_r[(size_t)(m0 + r) * HID + k0 + cc * 8]);
                cp_async16(&sAl[buf * P_A_E + r * 136 + cc * 8],
                           &Al_r[(size_t)(m0 + r) * HID + k0 + cc * 8]);
            }
        };
        auto stageB = [&](int c, int buf) {
            const int k0 = c * 128;
            #pragma unroll
            for (int i = 0; i < 4; i++) {
                int p = tid + i * 256, r = p >> 4, cc = p & 15;
                cp_async16(&sBlo[buf * P_BLO_E + r * 136 + cc * 8],
                           &g_BTlo[(size_t)(n0 + r) * HID + k0 + cc * 8]);
            }
        };

        // (1) Blo pre-stage for first two chunks (h-independent, never blocks)
        stageB(rc(0), 0);
        stageB(rc(1), 1);
        cp_commit();                               // G1

        // (2) xp prefetch (ks==0 half only; no cross-CTA dependency)
        float2 xv[8];
        if (ks == 0) {
            #pragma unroll
            for (int rr = 0; rr < 2; rr++)
                #pragma unroll
                for (int nt = 0; nt < 4; nt++)
                    xv[rr * 4 + nt] = *reinterpret_cast<const float2*>(
                        &xp[(size_t)(m_e0 + rr * 8) * HID + n_e0 + nt * 8]);
        }

        // (3) concurrent polling: warp w covers chunk rc(w)
        {
            const int c = rc(wid);
            const unsigned need = (unsigned)(t - 1);
            const int p0 = 2 * c, p1 = 2 * c + 1;
            if (p0 != ng) poll_gpu(&g_barv[mg][p0], need);
            if (p1 != ng) poll_gpu(&g_barv[mg][p1], need);
            if (lane == 0) {
                unsigned a = (unsigned)__cvta_generic_to_shared(&rdy[c]);
                asm volatile("st.release.cta.shared::cta.b32 [%0], %1;" :: "r"(a), "r"(1u));
            }
        }

        // (4) stage A for first chunk once its producers are confirmed
        wait_flag(&rdy[rc(0)]);
        stageA(rc(0), 0); cp_commit();             // G2

        float c1[4][4], c2[4][4], c3[4][4];
        #pragma unroll
        for (int i = 0; i < 4; i++)
            #pragma unroll
            for (int j = 0; j < 4; j++) { c1[i][j] = 0.f; c2[i][j] = 0.f; c3[i][j] = 0.f; }

        for (int kt = 0; kt < 8; kt++) {
            const int buf = kt & 1;
            const int c = rc(kt);
            if (kt < 7) {
                const int cn = rc(kt + 1);
                wait_flag(&rdy[cn]);
                stageA(cn, (kt + 1) & 1);
                if (kt + 1 >= 2) stageB(cn, (kt + 1) & 1);
                cp_commit(); cp_wait<1>();
            } else {
                cp_commit(); cp_wait<0>();
            }
            __syncthreads();

            #pragma unroll
            for (int kkj = 0; kkj < 4; kkj++) {
                const int kk = kkj * 32 + ks * 16;
                unsigned ah[4], al[4], bh[8], bl[8];
                ldsm_x4(ah[0], ah[1], ah[2], ah[3],
                        &sAh[buf * P_A_E + a_row * 136 + kk + a_cs]);
                ldsm_x4(al[0], al[1], al[2], al[3],
                        &sAl[buf * P_A_E + a_row * 136 + kk + a_cs]);
                #pragma unroll
                for (int p = 0; p < 2; p++) {
                    const int nb = wn * 32 + p * 16 + b_sub;
                    ldsm_x4(bh[p * 4 + 0], bh[p * 4 + 1], bh[p * 4 + 2], bh[p * 4 + 3],
                            &sBper[nb * 1032 + c * 128 + kk + b_cs]);
                    ldsm_x4(bl[p * 4 + 0], bl[p * 4 + 1], bl[p * 4 + 2], bl[p * 4 + 3],
                            &sBlo[buf * P_BLO_E + nb * 136 + kk + b_cs]);
                }
                #pragma unroll
                for (int nt = 0; nt < 4; nt++) {
                    const int p = nt >> 1, q = (nt & 1) * 2;
                    mma_bf16(c1[nt], ah, bh[p * 4 + q], bh[p * 4 + q + 1]);
                    mma_bf16(c2[nt], ah, bl[p * 4 + q], bl[p * 4 + q + 1]);
                    mma_bf16(c3[nt], al, bh[p * 4 + q], bh[p * 4 + q + 1]);
                }
            }
            __syncthreads();
        }

        // reset next-step parity flags (no reader until after epilogue syncs)
        if (tid < 8) sReady[(1 - par) * 8 + tid] = 0;

        // ---- epilogue: combine K-split halves, tanh, split, store
        float cs[4][4];
        #pragma unroll
        for (int nt = 0; nt < 4; nt++)
            #pragma unroll
            for (int j = 0; j < 4; j++)
                cs[nt][j] = c1[nt][j] + c2[nt][j] + c3[nt][j];

        if (ks == 1) {
            #pragma unroll
            for (int nt = 0; nt < 4; nt++)
                #pragma unroll
                for (int j = 0; j < 4; j++)
                    sRed[(pos * 32 + lane) * 17 + nt * 4 + j] = cs[nt][j];
        }
        __syncthreads();

        if (ks == 0) {
            #pragma unroll
            for (int nt = 0; nt < 4; nt++) {
                #pragma unroll
                for (int rr = 0; rr < 2; rr++) {
                    float p0 = sRed[(pos * 32 + lane) * 17 + nt * 4 + rr * 2 + 0];
                    float p1 = sRed[(pos * 32 + lane) * 17 + nt * 4 + rr * 2 + 1];
                    float2 x2 = xv[rr * 4 + nt];
                    float z0 = cs[nt][rr * 2 + 0] + p0 + x2.x;
                    float z1 = cs[nt][rr * 2 + 1] + p1 + x2.y;
                    float h0 = tanhf(z0), h1 = tanhf(z1);
                    __nv_bfloat16 hi0, lo0, hi1, lo1;
                    split2(h0, hi0, lo0); split2(h1, hi1, lo1);
                    __nv_bfloat162 vh; vh.x = hi0; vh.y = hi1;
                    __nv_bfloat162 vl; vl.x = lo0; vl.y = lo1;
                    size_t off = (size_t)(m_e0 + rr * 8) * HID + n_e0 + nt * 8;
                    *reinterpret_cast<__nv_bfloat162*>(&Ah_w[off]) = vh;
                    *reinterpret_cast<__nv_bfloat162*>(&Al_w[off]) = vl;
                }
            }
        }
        __syncthreads();
        if (tid == 0)
            asm volatile("red.release.gpu.add.u32 [%0], %1;"
                         :: "l"(&g_barv[mg][ng]), "r"(1u));
    }
}

// ---------------------------------------------------------------------------
// Output: logits = h_final @ Why + bo; softmax. One warp per batch row.
// ---------------------------------------------------------------------------
__global__ void out_kernel(const float* __restrict__ Why,
                           const float* __restrict__ bo,
                           float* __restrict__ out)
{
    const int b = blockIdx.x, lane = threadIdx.x;
    const __nv_bfloat16* __restrict__ hh = g_Ahi[(SEQ - 1) & 1];
    const __nv_bfloat16* __restrict__ hl = g_Alo[(SEQ - 1) & 1];

    float acc[NOUT] = {};
    for (int k = lane; k < HID; k += 32) {
        float hv = __bfloat162float(hh[(size_t)b * HID + k]) +
                   __bfloat162float(hl[(size_t)b * HID + k]);
        #pragma unroll
        for (int o = 0; o < NOUT; o++)
            acc[o] += hv * Why[k * NOUT + o];
    }
    #pragma unroll
    for (int o = 0; o < NOUT; o++) {
        #pragma unroll
        for (int s = 16; s; s >>= 1)
            acc[o] += __shfl_xor_sync(0xffffffffu, acc[o], s);
        acc[o] += bo[o];
    }
    if (lane == 0) {
        float mx = acc[0];
        #pragma unroll
        for (int o = 1; o < NOUT; o++) mx = fmaxf(mx, acc[o]);
        float sum = 0.f, e[NOUT];
        #pragma unroll
        for (int o = 0; o < NOUT; o++) { e[o] = expf(acc[o] - mx); sum += e[o]; }
        float inv = 1.0f / sum;
        #pragma unroll
        for (int o = 0; o < NOUT; o++) out[b * NOUT + o] = e[o] * inv;
    }
}

// ---------------------------------------------------------------------------
extern "C" void kernel_launch(void* const* d_in, const int* in_sizes, int n_in,
                              void* d_out, int out_size)
{
    const float* x   = (const float*)d_in[0];
    const float* Whx = (const float*)d_in[1];
    const float* Whh = (const float*)d_in[2];
    const float* bh  = (const float*)d_in[3];
    const float* Why = (const float*)d_in[4];
    const float* bo  = (const float*)d_in[5];
    float* out = (float*)d_out;

    cudaFuncSetAttribute(xproj_mma_kernel,
                         cudaFuncAttributeMaxDynamicSharedMemorySize, XP_SMEM);
    cudaFuncSetAttribute(rnn_persist_kernel,
                         cudaFuncAttributeMaxDynamicSharedMemorySize, P_SMEM);

    split_whh_kernel<<<dim3(HID / 32, HID / 32), dim3(32, 8)>>>(Whh);
    split_whx_kernel<<<dim3(HID / 32, IN_DIM / 32), dim3(32, 8)>>>(Whx);
    xsplit_kernel<<<(MROWS * IN_DIM) / 1024, 256>>>(x);

    xproj_mma_kernel<<<dim3(HID / 256, MROWS / 256), 256, XP_SMEM>>>(bh);

    step0_kernel<<<(BATCH * HID) / 1024, 1024>>>();

    rnn_persist_kernel<<<128, 256, P_SMEM>>>();

    out_kernel<<<BATCH, 32>>>(Why, bo, out);
}

// round 15
// speedup vs baseline: 1.0829x; 1.0829x over previous
#include <cuda_runtime.h>
#include <cuda_bf16.h>
#include <math.h>

#define BATCH  256
#define SEQ    256
#define IN_DIM 128
#define HID    1024
#define NOUT   10
#define MROWS  (BATCH * SEQ)

// ---------------------------------------------------------------------------
// Global scratch
// ---------------------------------------------------------------------------
__device__ float g_xproj[(size_t)SEQ * BATCH * HID];                  // [s][b][h] fp32
__device__ __align__(16) __nv_bfloat16 g_Ahi[2][BATCH * HID];         // h hi (ping-pong)
__device__ __align__(16) __nv_bfloat16 g_Alo[2][BATCH * HID];         // h lo
__device__ __align__(16) __nv_bfloat16 g_BThi[HID * HID];             // Whh^T hi [n][k]
__device__ __align__(16) __nv_bfloat16 g_BTlo[HID * HID];             // Whh^T lo [n][k]
__device__ __align__(16) __nv_bfloat16 g_BXhi[HID * IN_DIM];          // Whx^T hi [n][k]
__device__ __align__(16) __nv_bfloat16 g_BXlo[HID * IN_DIM];          // Whx^T lo [n][k]
__device__ __align__(16) __nv_bfloat16 g_Xhi[(size_t)MROWS * IN_DIM]; // x hi [m][k]
__device__ __align__(16) __nv_bfloat16 g_Xlo[(size_t)MROWS * IN_DIM]; // x lo
__device__ unsigned g_bar[8];                                         // per-mg step counters
__device__ unsigned g_xpdone[SEQ];                                    // per-t xproj counters

// ---------------------------------------------------------------------------
// helpers
// ---------------------------------------------------------------------------
__device__ __forceinline__ void cp_async16(void* smem_dst, const void* gmem_src) {
    unsigned sa = (unsigned)__cvta_generic_to_shared(smem_dst);
    asm volatile("cp.async.cg.shared.global [%0], [%1], 16;\n" :: "r"(sa), "l"(gmem_src));
}
__device__ __forceinline__ void cp_commit() { asm volatile("cp.async.commit_group;\n"); }
template <int N>
__device__ __forceinline__ void cp_wait() { asm volatile("cp.async.wait_group %0;\n" :: "n"(N)); }

__device__ __forceinline__ void ldsm_x4(unsigned& r0, unsigned& r1, unsigned& r2, unsigned& r3,
                                        const void* p) {
    unsigned a = (unsigned)__cvta_generic_to_shared(p);
    asm volatile("ldmatrix.sync.aligned.m8n8.x4.shared.b16 {%0,%1,%2,%3}, [%4];"
                 : "=r"(r0), "=r"(r1), "=r"(r2), "=r"(r3) : "r"(a));
}
__device__ __forceinline__ void mma_bf16(float* c, const unsigned* a, unsigned b0, unsigned b1) {
    asm volatile(
        "mma.sync.aligned.m16n8k16.row.col.f32.bf16.bf16.f32 "
        "{%0,%1,%2,%3}, {%4,%5,%6,%7}, {%8,%9}, {%0,%1,%2,%3};"
        : "+f"(c[0]), "+f"(c[1]), "+f"(c[2]), "+f"(c[3])
        : "r"(a[0]), "r"(a[1]), "r"(a[2]), "r"(a[3]), "r"(b0), "r"(b1));
}
__device__ __forceinline__ void split2(float v, __nv_bfloat16& hi, __nv_bfloat16& lo) {
    hi = __float2bfloat16(v);
    lo = __float2bfloat16(v - __bfloat162float(hi));
}
__device__ __forceinline__ void poll_gpu(const unsigned* p, unsigned need) {
    unsigned v;
    do {
        asm volatile("ld.acquire.gpu.u32 %0, [%1];" : "=r"(v) : "l"(p));
    } while (v < need);
}

// ---------------------------------------------------------------------------
// Prep kernels: weight splits (transposed), x split, counter reset
// ---------------------------------------------------------------------------
__global__ __launch_bounds__(256) void split_whh_kernel(const float* __restrict__ W)
{
    __shared__ float tile[32][33];
    const int n0 = blockIdx.x * 32, k0 = blockIdx.y * 32;
    const int tx = threadIdx.x, ty = threadIdx.y;
    #pragma unroll
    for (int i = 0; i < 4; i++)
        tile[ty + i * 8][tx] = W[(size_t)(k0 + ty + i * 8) * HID + n0 + tx];
    __syncthreads();
    #pragma unroll
    for (int i = 0; i < 4; i++) {
        int n = n0 + ty + i * 8, k = k0 + tx;
        __nv_bfloat16 hi, lo; split2(tile[tx][ty + i * 8], hi, lo);
        g_BThi[(size_t)n * HID + k] = hi;
        g_BTlo[(size_t)n * HID + k] = lo;
    }
}

__global__ __launch_bounds__(256) void split_whx_kernel(const float* __restrict__ W)
{
    __shared__ float tile[32][33];
    const int n0 = blockIdx.x * 32, k0 = blockIdx.y * 32;
    const int tx = threadIdx.x, ty = threadIdx.y;
    #pragma unroll
    for (int i = 0; i < 4; i++)
        tile[ty + i * 8][tx] = W[(size_t)(k0 + ty + i * 8) * HID + n0 + tx];
    __syncthreads();
    #pragma unroll
    for (int i = 0; i < 4; i++) {
        int n = n0 + ty + i * 8, k = k0 + tx;
        __nv_bfloat16 hi, lo; split2(tile[tx][ty + i * 8], hi, lo);
        g_BXhi[(size_t)n * IN_DIM + k] = hi;
        g_BXlo[(size_t)n * IN_DIM + k] = lo;
    }
}

__global__ __launch_bounds__(256) void xsplit_kernel(const float* __restrict__ x)
{
    size_t i = ((size_t)blockIdx.x * 256 + threadIdx.x) * 4;
    float4 v = *reinterpret_cast<const float4*>(&x[i]);
    __nv_bfloat16 h0,h1,h2,h3,l0,l1,l2,l3;
    split2(v.x,h0,l0); split2(v.y,h1,l1); split2(v.z,h2,l2); split2(v.w,h3,l3);
    __nv_bfloat162 a,b,c,d;
    a.x=h0; a.y=h1; b.x=h2; b.y=h3; c.x=l0; c.y=l1; d.x=l2; d.y=l3;
    *reinterpret_cast<__nv_bfloat162*>(&g_Xhi[i])     = a;
    *reinterpret_cast<__nv_bfloat162*>(&g_Xhi[i + 2]) = b;
    *reinterpret_cast<__nv_bfloat162*>(&g_Xlo[i])     = c;
    *reinterpret_cast<__nv_bfloat162*>(&g_Xlo[i + 2]) = d;
}

__global__ void reset_kernel()
{
    int i = threadIdx.x;
    if (i < 8)   g_bar[i] = 0;
    if (i < SEQ) g_xpdone[i] = 0;
}

// ---------------------------------------------------------------------------
// Fused persistent kernel: 144 CTAs.
//   CTAs 0..127  : RNN consumers (8 mg x 16 ng), exact R11 structure.
//   CTAs 128..143: xproj producers, 16 units of (64 b-rows x 256 n-cols),
//                  marching t = 0..255, publishing g_xpdone[t].
// ---------------------------------------------------------------------------
#define P_BPER_E (64 * 1032)
#define P_BLO_E  (64 * 136)
#define P_A_E    (32 * 136)
#define RNN_SMEM ((P_BPER_E + 2 * P_BLO_E + 4 * P_A_E) * 2 + 4 * 32 * 17 * 4)
#define XP_BE    (256 * 136)
#define XP_AE    (64 * 136)
#define PROD_SMEM ((2 * XP_BE + 4 * XP_AE) * 2)
#define FS_SMEM  (RNN_SMEM > PROD_SMEM ? RNN_SMEM : PROD_SMEM)

__device__ __forceinline__ void rnn_role(char* sm_raw)
{
    __nv_bfloat16* sBper = (__nv_bfloat16*)sm_raw;       // [64][1032]
    __nv_bfloat16* sBlo  = sBper + P_BPER_E;             // [2][64][136]
    __nv_bfloat16* sAh   = sBlo + 2 * P_BLO_E;           // [2][32][136]
    __nv_bfloat16* sAl   = sAh + 2 * P_A_E;              // [2][32][136]
    float*         sRed  = (float*)(sAl + 2 * P_A_E);    // [4][32][17]

    const int bx = blockIdx.x;
    const int ng = bx >> 3, mg = bx & 7;
    const int n0 = ng * 64, m0 = mg * 32;

    const int tid = threadIdx.x, lane = tid & 31, wid = tid >> 5;
    const int wm = wid & 1;            // M position (16 rows)
    const int wn = (wid >> 1) & 1;     // N position (32 cols)
    const int ks = wid >> 2;           // K-split half
    const int pos = wm * 2 + wn;
    const int lt = lane >> 3, lr = lane & 7;
    const int g = lane >> 2, t2 = (lane & 3) * 2;
    const int a_row = wm * 16 + (lt & 1) * 8 + lr;
    const int a_cs  = (lt >> 1) * 8;
    const int b_sub = (lt >> 1) * 8 + lr;
    const int b_cs  = (lt & 1) * 8;
    const int m_e0  = m0 + wm * 16 + g;
    const int n_e0  = n0 + wn * 32 + t2;

    // ---- load persistent Whh^T hi slice (64 x 1024)
    #pragma unroll
    for (int i = 0; i < 32; i++) {
        int p = tid + i * 256, r = p >> 7, c = p & 127;
        cp_async16(&sBper[r * 1032 + c * 8], &g_BThi[(size_t)(n0 + r) * HID + c * 8]);
    }
    cp_commit(); cp_wait<0>(); __syncthreads();

    // ---- h0 = tanh(xp[0]) for this CTA's 32x64 tile
    if (tid == 0) poll_gpu(&g_xpdone[0], 16);
    __syncthreads();
    {
        const float* __restrict__ xp0 = g_xproj;
        #pragma unroll
        for (int i = 0; i < 4; i++) {
            int p = tid + i * 256;
            int r = p >> 5, c2 = p & 31;       // 32 rows x 32 float2
            float2 v = *reinterpret_cast<const float2*>(
                &xp0[(size_t)(m0 + r) * HID + n0 + c2 * 2]);
            float h0 = tanhf(v.x), h1 = tanhf(v.y);
            __nv_bfloat16 hi0, lo0, hi1, lo1;
            split2(h0, hi0, lo0); split2(h1, hi1, lo1);
            __nv_bfloat162 vh; vh.x = hi0; vh.y = hi1;
            __nv_bfloat162 vl; vl.x = lo0; vl.y = lo1;
            size_t off = (size_t)(m0 + r) * HID + n0 + c2 * 2;
            *reinterpret_cast<__nv_bfloat162*>(&g_Ahi[0][off]) = vh;
            *reinterpret_cast<__nv_bfloat162*>(&g_Alo[0][off]) = vl;
        }
    }
    __syncthreads();
    if (tid == 0)
        asm volatile("red.release.gpu.add.u32 [%0], %1;" :: "l"(&g_bar[mg]), "r"(1u));

    // ---- main loop
    for (int t = 1; t < SEQ; t++) {
        const __nv_bfloat16* __restrict__ Ah_r = g_Ahi[(t - 1) & 1];
        const __nv_bfloat16* __restrict__ Al_r = g_Alo[(t - 1) & 1];
        __nv_bfloat16* __restrict__ Ah_w = g_Ahi[t & 1];
        __nv_bfloat16* __restrict__ Al_w = g_Alo[t & 1];
        const float* __restrict__ xp = &g_xproj[(size_t)t * BATCH * HID];

        auto stageA = [&](int kt, int buf) {
            const int k0 = kt * 128;
            #pragma unroll
            for (int i = 0; i < 2; i++) {
                int p = tid + i * 256, r = p >> 4, cc = p & 15;
                cp_async16(&sAh[buf * P_A_E + r * 136 + cc * 8],
                           &Ah_r[(size_t)(m0 + r) * HID + k0 + cc * 8]);
                cp_async16(&sAl[buf * P_A_E + r * 136 + cc * 8],
                           &Al_r[(size_t)(m0 + r) * HID + k0 + cc * 8]);
            }
        };
        auto stageB = [&](int kt, int buf) {
            const int k0 = kt * 128;
            #pragma unroll
            for (int i = 0; i < 4; i++) {
                int p = tid + i * 256, r = p >> 4, cc = p & 15;
                cp_async16(&sBlo[buf * P_BLO_E + r * 136 + cc * 8],
                           &g_BTlo[(size_t)(n0 + r) * HID + k0 + cc * 8]);
            }
        };

        // Blo pre-stage (h-independent)
        stageB(0, 0);
        stageB(1, 1);
        cp_commit();                               // G1

        // wait for xp[t] and for step t-1 writers of this M-group
        if (tid == 0) {
            poll_gpu(&g_xpdone[t], 16);
            poll_gpu(&g_bar[mg], 16u * (unsigned)t);
        }
        __syncthreads();

        // xp prefetch (ks==0 half only)
        float2 xv[8];
        if (ks == 0) {
            #pragma unroll
            for (int rr = 0; rr < 2; rr++)
                #pragma unroll
                for (int nt = 0; nt < 4; nt++)
                    xv[rr * 4 + nt] = *reinterpret_cast<const float2*>(
                        &xp[(size_t)(m_e0 + rr * 8) * HID + n_e0 + nt * 8]);
        }

        stageA(0, 0); cp_commit();                 // G2

        float c1[4][4], c2[4][4], c3[4][4];
        #pragma unroll
        for (int i = 0; i < 4; i++)
            #pragma unroll
            for (int j = 0; j < 4; j++) { c1[i][j] = 0.f; c2[i][j] = 0.f; c3[i][j] = 0.f; }

        for (int kt = 0; kt < 8; kt++) {
            const int buf = kt & 1;
            if (kt < 7) {
                stageA(kt + 1, (kt + 1) & 1);
                if (kt + 1 >= 2) stageB(kt + 1, (kt + 1) & 1);
                cp_commit(); cp_wait<1>();
            } else {
                cp_commit(); cp_wait<0>();
            }
            __syncthreads();

            #pragma unroll
            for (int kkj = 0; kkj < 4; kkj++) {
                const int kk = kkj * 32 + ks * 16;
                unsigned ah[4], al[4], bh[8], bl[8];
                ldsm_x4(ah[0], ah[1], ah[2], ah[3],
                        &sAh[buf * P_A_E + a_row * 136 + kk + a_cs]);
                ldsm_x4(al[0], al[1], al[2], al[3],
                        &sAl[buf * P_A_E + a_row * 136 + kk + a_cs]);
                #pragma unroll
                for (int p = 0; p < 2; p++) {
                    const int nb = wn * 32 + p * 16 + b_sub;
                    ldsm_x4(bh[p * 4 + 0], bh[p * 4 + 1], bh[p * 4 + 2], bh[p * 4 + 3],
                            &sBper[nb * 1032 + kt * 128 + kk + b_cs]);
                    ldsm_x4(bl[p * 4 + 0], bl[p * 4 + 1], bl[p * 4 + 2], bl[p * 4 + 3],
                            &sBlo[buf * P_BLO_E + nb * 136 + kk + b_cs]);
                }
                #pragma unroll
                for (int nt = 0; nt < 4; nt++) {
                    const int p = nt >> 1, q = (nt & 1) * 2;
                    mma_bf16(c1[nt], ah, bh[p * 4 + q], bh[p * 4 + q + 1]);
                    mma_bf16(c2[nt], ah, bl[p * 4 + q], bl[p * 4 + q + 1]);
                    mma_bf16(c3[nt], al, bh[p * 4 + q], bh[p * 4 + q + 1]);
                }
            }
            __syncthreads();
        }

        // ---- epilogue: combine K-split halves, tanh, split, store
        float cs[4][4];
        #pragma unroll
        for (int nt = 0; nt < 4; nt++)
            #pragma unroll
            for (int j = 0; j < 4; j++)
                cs[nt][j] = c1[nt][j] + c2[nt][j] + c3[nt][j];

        if (ks == 1) {
            #pragma unroll
            for (int nt = 0; nt < 4; nt++)
                #pragma unroll
                for (int j = 0; j < 4; j++)
                    sRed[(pos * 32 + lane) * 17 + nt * 4 + j] = cs[nt][j];
        }
        __syncthreads();

        if (ks == 0) {
            #pragma unroll
            for (int nt = 0; nt < 4; nt++) {
                #pragma unroll
                for (int rr = 0; rr < 2; rr++) {
                    float p0 = sRed[(pos * 32 + lane) * 17 + nt * 4 + rr * 2 + 0];
                    float p1 = sRed[(pos * 32 + lane) * 17 + nt * 4 + rr * 2 + 1];
                    float2 x2 = xv[rr * 4 + nt];
                    float z0 = cs[nt][rr * 2 + 0] + p0 + x2.x;
                    float z1 = cs[nt][rr * 2 + 1] + p1 + x2.y;
                    float h0 = tanhf(z0), h1 = tanhf(z1);
                    __nv_bfloat16 hi0, lo0, hi1, lo1;
                    split2(h0, hi0, lo0); split2(h1, hi1, lo1);
                    __nv_bfloat162 vh; vh.x = hi0; vh.y = hi1;
                    __nv_bfloat162 vl; vl.x = lo0; vl.y = lo1;
                    size_t off = (size_t)(m_e0 + rr * 8) * HID + n_e0 + nt * 8;
                    *reinterpret_cast<__nv_bfloat162*>(&Ah_w[off]) = vh;
                    *reinterpret_cast<__nv_bfloat162*>(&Al_w[off]) = vl;
                }
            }
        }
        __syncthreads();
        if (tid == 0)
            asm volatile("red.release.gpu.add.u32 [%0], %1;"
                         :: "l"(&g_bar[mg]), "r"(1u));
    }
}

__device__ __forceinline__ void xproj_role(char* sm_raw, int pid, const float* __restrict__ bh)
{
    __nv_bfloat16* sBh = (__nv_bfloat16*)sm_raw;     // [256][136]
    __nv_bfloat16* sBl = sBh + XP_BE;
    __nv_bfloat16* sAh = sBl + XP_BE;                // [2][64][136]
    __nv_bfloat16* sAl = sAh + 2 * XP_AE;

    const int mb = pid & 3;                // 64 b-rows
    const int nb = pid >> 2;               // 256 n-cols
    const int n0 = nb * 256;
    const int tid = threadIdx.x, lane = tid & 31, wid = tid >> 5;
    const int wm = wid >> 2, wn = wid & 3;
    const int lt = lane >> 3, lr = lane & 7;
    const int g = lane >> 2, t2 = (lane & 3) * 2;
    const int a_sub = (lt & 1) * 8 + lr, a_cs = (lt >> 1) * 8;
    const int b_sub = (lt >> 1) * 8 + lr, b_cs = (lt & 1) * 8;

    // bias for this CTA's n-columns (per nt), loop-invariant
    float2 bias[8];
    #pragma unroll
    for (int nt = 0; nt < 8; nt++)
        bias[nt] = *reinterpret_cast<const float2*>(&bh[n0 + wn * 64 + nt * 8 + t2]);

    auto stageA = [&](int t, int buf) {
        #pragma unroll
        for (int i = 0; i < 4; i++) {
            int p = tid + i * 256, r = p >> 4, cc = p & 15;
            size_t m = (size_t)(mb * 64 + r) * SEQ + t;
            cp_async16(&sAh[buf * XP_AE + r * 136 + cc * 8], &g_Xhi[m * IN_DIM + cc * 8]);
            cp_async16(&sAl[buf * XP_AE + r * 136 + cc * 8], &g_Xlo[m * IN_DIM + cc * 8]);
        }
    };

    // persist B slice + stage A for t=0
    #pragma unroll
    for (int i = 0; i < 16; i++) {
        int p = tid + i * 256, r = p >> 4, c = p & 15;
        cp_async16(&sBh[r * 136 + c * 8], &g_BXhi[(size_t)(n0 + r) * IN_DIM + c * 8]);
        cp_async16(&sBl[r * 136 + c * 8], &g_BXlo[(size_t)(n0 + r) * IN_DIM + c * 8]);
    }
    stageA(0, 0);
    cp_commit();

    for (int t = 0; t < SEQ; t++) {
        const int buf = t & 1;
        if (t + 1 < SEQ) { stageA(t + 1, (t + 1) & 1); cp_commit(); cp_wait<1>(); }
        else             { cp_wait<0>(); }
        __syncthreads();

        float c_[2][8][4];
        #pragma unroll
        for (int i = 0; i < 2; i++)
            #pragma unroll
            for (int j = 0; j < 8; j++)
                #pragma unroll
                for (int q = 0; q < 4; q++) c_[i][j][q] = 0.f;

        #pragma unroll
        for (int kk = 0; kk < IN_DIM; kk += 16) {
            unsigned ah2[2][4], al2[2][4], bhf[4][4], blf[4][4];
            #pragma unroll
            for (int mi = 0; mi < 2; mi++) {
                int row = wm * 32 + mi * 16 + a_sub;
                ldsm_x4(ah2[mi][0], ah2[mi][1], ah2[mi][2], ah2[mi][3],
                        &sAh[buf * XP_AE + row * 136 + kk + a_cs]);
                ldsm_x4(al2[mi][0], al2[mi][1], al2[mi][2], al2[mi][3],
                        &sAl[buf * XP_AE + row * 136 + kk + a_cs]);
            }
            #pragma unroll
            for (int p = 0; p < 4; p++) {
                int row = wn * 64 + p * 16 + b_sub;
                ldsm_x4(bhf[p][0], bhf[p][1], bhf[p][2], bhf[p][3], &sBh[row * 136 + kk + b_cs]);
                ldsm_x4(blf[p][0], blf[p][1], blf[p][2], blf[p][3], &sBl[row * 136 + kk + b_cs]);
            }
            #pragma unroll
            for (int mi = 0; mi < 2; mi++)
                #pragma unroll
                for (int nt = 0; nt < 8; nt++) {
                    int p = nt >> 1, q = (nt & 1) * 2;
                    mma_bf16(c_[mi][nt], ah2[mi], bhf[p][q], bhf[p][q + 1]);
                    mma_bf16(c_[mi][nt], ah2[mi], blf[p][q], blf[p][q + 1]);
                    mma_bf16(c_[mi][nt], al2[mi], bhf[p][q], bhf[p][q + 1]);
                }
        }

        // write xp[t] tile + bias
        #pragma unroll
        for (int mi = 0; mi < 2; mi++)
            #pragma unroll
            for (int nt = 0; nt < 8; nt++) {
                int n_e = n0 + wn * 64 + nt * 8 + t2;
                #pragma unroll
                for (int rr = 0; rr < 2; rr++) {
                    int b = mb * 64 + wm * 32 + mi * 16 + g + rr * 8;
                    float2 o;
                    o.x = c_[mi][nt][rr * 2 + 0] + bias[nt].x;
                    o.y = c_[mi][nt][rr * 2 + 1] + bias[nt].y;
                    *reinterpret_cast<float2*>(
                        &g_xproj[((size_t)t * BATCH + b) * HID + n_e]) = o;
                }
            }

        __syncthreads();
        if (tid == 0)
            asm volatile("red.release.gpu.add.u32 [%0], %1;"
                         :: "l"(&g_xpdone[t]), "r"(1u));
    }
}

__global__ __launch_bounds__(256) void fused_kernel(const float* __restrict__ bh)
{
    extern __shared__ __align__(16) char sm_raw[];
    if (blockIdx.x < 128) rnn_role(sm_raw);
    else                  xproj_role(sm_raw, blockIdx.x - 128, bh);
}

// ---------------------------------------------------------------------------
// Output: logits = h_final @ Why + bo; softmax. One warp per batch row.
// ---------------------------------------------------------------------------
__global__ void out_kernel(const float* __restrict__ Why,
                           const float* __restrict__ bo,
                           float* __restrict__ out)
{
    const int b = blockIdx.x, lane = threadIdx.x;
    const __nv_bfloat16* __restrict__ hh = g_Ahi[(SEQ - 1) & 1];
    const __nv_bfloat16* __restrict__ hl = g_Alo[(SEQ - 1) & 1];

    float acc[NOUT] = {};
    for (int k = lane; k < HID; k += 32) {
        float hv = __bfloat162float(hh[(size_t)b * HID + k]) +
                   __bfloat162float(hl[(size_t)b * HID + k]);
        #pragma unroll
        for (int o = 0; o < NOUT; o++)
            acc[o] += hv * Why[k * NOUT + o];
    }
    #pragma unroll
    for (int o = 0; o < NOUT; o++) {
        #pragma unroll
        for (int s = 16; s; s >>= 1)
            acc[o] += __shfl_xor_sync(0xffffffffu, acc[o], s);
        acc[o] += bo[o];
    }
    if (lane == 0) {
        float mx = acc[0];
        #pragma unroll
        for (int o = 1; o < NOUT; o++) mx = fmaxf(mx, acc[o]);
        float sum = 0.f, e[NOUT];
        #pragma unroll
        for (int o = 0; o < NOUT; o++) { e[o] = expf(acc[o] - mx); sum += e[o]; }
        float inv = 1.0f / sum;
        #pragma unroll
        for (int o = 0; o < NOUT; o++) out[b * NOUT + o] = e[o] * inv;
    }
}

// ---------------------------------------------------------------------------
extern "C" void kernel_launch(void* const* d_in, const int* in_sizes, int n_in,
                              void* d_out, int out_size)
{
    const float* x   = (const float*)d_in[0];
    const float* Whx = (const float*)d_in[1];
    const float* Whh = (const float*)d_in[2];
    const float* bh  = (const float*)d_in[3];
    const float* Why = (const float*)d_in[4];
    const float* bo  = (const float*)d_in[5];
    float* out = (float*)d_out;

    cudaFuncSetAttribute(fused_kernel,
                         cudaFuncAttributeMaxDynamicSharedMemorySize, FS_SMEM);

    split_whh_kernel<<<dim3(HID / 32, HID / 32), dim3(32, 8)>>>(Whh);
    split_whx_kernel<<<dim3(HID / 32, IN_DIM / 32), dim3(32, 8)>>>(Whx);
    xsplit_kernel<<<(MROWS * IN_DIM) / 1024, 256>>>(x);
    reset_kernel<<<1, 256>>>();

    fused_kernel<<<144, 256, FS_SMEM>>>(bh);

    out_kernel<<<BATCH, 32>>>(Why, bo, out);
}